// round 10
// baseline (speedup 1.0000x reference)
#include <cuda_runtime.h>
#include <cstdint>

#define SIZE   128
#define EPSF   1e-6f
#define BW     3            // half bandwidth of final operators
#define TAPS   7            // 2*BW+1
#define CW     8            // padded Lb coeff row width
#define SBW    5            // single-solve inverse band half-width
#define GW     11           // 2*SBW+1
#define KBC    10           // chain band half-width (5-sweep products)
#define CBW    21           // chain band storage width
#define KBE    12           // E (10-sweep) band half-width
#define EW     25           // E band storage width
#define RSTRIP 64           // rows per band CTA
#define UROWS  (RSTRIP + 2 * BW)   // 70

// ---------------------------------------------------------------------------
// Globals
// ---------------------------------------------------------------------------
// banded chains: 0..3 = X chains C1..C4 (W = C1*C2*C3*C4), 4 = Q1, 5 = Q2 (L = Q2*Q1)
__device__ float g_cb[6][SIZE * CBW];
__device__ float g_Lb[SIZE * CW];          // row-major padded
__device__ float g_WbT[TAPS * SIZE];       // tap-major: WbT[d][j] = W[j-BW+d][j]

// ---------------------------------------------------------------------------
// setup_ops: 6 CTAs, one per 5-sweep chain. No serial Thomas application:
// per sweep, compute θ/φ recurrences (10 independent 128-step chains, run
// in parallel threads), evaluate the banded inverse in closed form
//   (M^-1)_{ij} = (Π_{k} co_k) θ_{i-1} φ_{j+1} / θ_{n-1}
// then compose the 5 banded inverses with parallel band products.
// X parts 0..3 (tile <- tile * G^T, right-mult), Y parts 4..5 (left-mult).
// X chain part p covers X-order sweeps [5p,5p+5); m-th X sweep: k=m>>1,
// t=(k+(m&1))*DT, dt=DT/2. Y parts: m-th Y sweep t=m*DT+DT/2, dt=DT.
// ---------------------------------------------------------------------------
__global__ void __launch_bounds__(128, 1)
setup_ops_kernel(const float* __restrict__ abx, const float* __restrict__ atx,
                 const float* __restrict__ aqx, const float* __restrict__ bby,
                 const float* __restrict__ bty, const float* __restrict__ bqy)
{
    extern __shared__ float sh[];
    float* co   = sh;                     // 5*128 coefficients
    float* th   = co + 5 * SIZE;          // 5*130: th[q*130+i+1] = theta_i (i=-1..127)
    float* ph   = th + 5 * 130;           // 5*130: ph[q*130+j]   = phi_j   (j=0..128)
    float* gb   = ph + 5 * 130;           // 5*128*GW banded inverses
    float* accS = gb + 5 * SIZE * GW;     // 128*CBW chain accumulator

    const int tid  = threadIdx.x;
    const int part = blockIdx.x;
    const bool isY = part >= 4;

    // ---- 1. coefficients (parallel) ----
    #pragma unroll 1
    for (int q = 0; q < 5; q++) {
        int m = isY ? (part - 4) * 5 + q : part * 5 + q;
        float t, dt; const float *bp, *lp, *qp;
        if (isY) { t = m * 0.01f + 0.005f;                    dt = 0.01f;  bp = bby; lp = bty; qp = bqy; }
        else     { int k = m >> 1; t = (k + (m & 1)) * 0.01f; dt = 0.005f; bp = abx; lp = atx; qp = aqx; }
        int i = tid;
        int im = max(i - 1, 0), ip = min(i + 1, 127);
        float vm = fmaxf(bp[im] + lp[im] * t + qp[im] * t * t, EPSF);
        float vc = fmaxf(bp[i]  + lp[i]  * t + qp[i]  * t * t, EPSF);
        float vp = fmaxf(bp[ip] + lp[ip] * t + qp[ip] * t * t, EPSF);
        co[q * SIZE + i] = (vm + vc + vp) * (1.0f / 3.0f) * dt;
    }
    __syncthreads();

    // ---- 2. theta (lanes 0..4 of warp 0) and phi (lanes 0..4 of warp 1) ----
    if (tid < 5) {
        const int q = tid;
        const float* c = &co[q * SIZE];
        float t2 = 1.0f;                       // theta_{-1}
        float cprev = c[0];
        float t1 = 1.0f + cprev;               // theta_0 = b_0 = 1+c0
        th[q * 130 + 0] = 1.0f;
        th[q * 130 + 1] = t1;
        #pragma unroll 4
        for (int i = 1; i < SIZE; i++) {
            float ci = c[i];
            float bi = (i == SIZE - 1) ? (1.0f + ci) : (1.0f + 2.0f * ci);
            float tn = bi * t1 - (ci * cprev) * t2;
            th[q * 130 + i + 1] = tn;
            t2 = t1; t1 = tn; cprev = ci;
        }
    } else if (tid >= 32 && tid < 37) {
        const int q = tid - 32;
        const float* c = &co[q * SIZE];
        float p2 = 1.0f;                       // phi_128
        float cnext = c[SIZE - 1];
        float p1 = 1.0f + cnext;               // phi_127 = b_127
        ph[q * 130 + 128] = 1.0f;
        ph[q * 130 + 127] = p1;
        #pragma unroll 4
        for (int i = SIZE - 2; i >= 0; i--) {
            float ci = c[i];
            float bi = (i == 0) ? (1.0f + ci) : (1.0f + 2.0f * ci);
            float pn = bi * p1 - (ci * cnext) * p2;
            ph[q * 130 + i] = pn;
            p2 = p1; p1 = pn; cnext = ci;
        }
    }
    __syncthreads();

    // ---- 3. banded inverses (parallel over rows) ----
    const int i = tid;
    #pragma unroll 1
    for (int q = 0; q < 5; q++) {
        const float invthn = 1.0f / th[q * 130 + 128];   // theta_{127}
        #pragma unroll
        for (int e = 0; e < GW; e++) {
            int j = i - SBW + e;
            float g = 0.0f;
            if (j >= 0 && j < SIZE) {
                float prod = 1.0f;
                if (i <= j) {
                    for (int k = i; k < j; k++) prod *= co[q * SIZE + k];
                    g = prod * th[q * 130 + i] * ph[q * 130 + j + 1] * invthn;
                } else {
                    for (int k = j + 1; k <= i; k++) prod *= co[q * SIZE + k];
                    g = prod * th[q * 130 + j] * ph[q * 130 + i + 1] * invthn;
                }
            }
            gb[(q * SIZE + i) * GW + e] = g;
        }
    }
    __syncthreads();

    // ---- 4. chain product (banded, parallel) ----
    // X: Acc <- Acc * Gq^T   (Gq^T[k][c] = G[c][k])
    // Y: Acc <- Gq * Acc
    {
        const int r = tid;
        #pragma unroll
        for (int o = 0; o < CBW; o++) {
            int c = r - KBC + o;
            float v = 0.0f;
            if (c >= 0 && c < SIZE && c - r >= -SBW && c - r <= SBW)
                v = isY ? gb[(0 * SIZE + r) * GW + (c - r + SBW)]
                        : gb[(0 * SIZE + c) * GW + (r - c + SBW)];
            accS[r * CBW + o] = v;
        }
    }
    __syncthreads();

    #pragma unroll 1
    for (int q = 1; q < 5; q++) {
        const int r = tid;
        float nw[CBW];
        #pragma unroll
        for (int o = 0; o < CBW; o++) {
            int c = r - KBC + o;
            float s = 0.0f;
            if (c >= 0 && c < SIZE) {
                if (isY) {
                    int klo = max(r - SBW, max(c - KBC, 0));
                    int khi = min(r + SBW, min(c + KBC, SIZE - 1));
                    for (int k = klo; k <= khi; k++)
                        s += gb[(q * SIZE + r) * GW + (k - r + SBW)]
                           * accS[k * CBW + (c - k + KBC)];
                } else {
                    int klo = max(c - SBW, max(r - KBC, 0));
                    int khi = min(c + SBW, min(r + KBC, SIZE - 1));
                    for (int k = klo; k <= khi; k++)
                        s += accS[r * CBW + (k - r + KBC)]
                           * gb[(q * SIZE + c) * GW + (k - c + SBW)];
                }
            }
            nw[o] = s;
        }
        __syncthreads();
        #pragma unroll
        for (int o = 0; o < CBW; o++) accS[r * CBW + o] = nw[o];
        __syncthreads();
    }

    for (int d = 0; d < CBW; d++)
        g_cb[part][tid * CBW + d] = accS[tid * CBW + d];
}

// ---------------------------------------------------------------------------
// setup3: band composition in one 1024-thread CTA.
// E1 = C1*C2, E2 = C3*C4 (band KBE); Lb = band_BW(Q2*Q1); WbT = band_BW(E1*E2)^T.
// ---------------------------------------------------------------------------
__global__ void __launch_bounds__(1024, 1) setup3_kernel()
{
    extern __shared__ float s3[];
    float* cb = s3;                      // 6*128*21
    float* E  = s3 + 6 * SIZE * CBW;     // 2*128*25
    const int tid = threadIdx.x;

    for (int m = tid; m < 6 * SIZE * CBW; m += 1024)
        cb[m] = ((const float*)g_cb)[m];
    __syncthreads();

    for (int idx = tid; idx < 2 * SIZE * EW; idx += 1024) {
        int e = idx / (SIZE * EW);
        int rem = idx - e * (SIZE * EW);
        int r = rem / EW, d = rem - r * EW;
        int c = r - KBE + d;
        float s = 0.0f;
        if (c >= 0 && c < SIZE) {
            const float* A = cb + (2 * e)     * SIZE * CBW;
            const float* B = cb + (2 * e + 1) * SIZE * CBW;
            int klo = max(max(r, c) - KBC, 0), khi = min(min(r, c) + KBC, 127);
            for (int k = klo; k <= khi; k++)
                s += A[r * CBW + (k - r + KBC)] * B[k * CBW + (c - k + KBC)];
        }
        E[idx] = s;
    }

    // Lb[i][d] = (Q2*Q1)[i][i-BW+d], padded to CW
    for (int idx = tid; idx < SIZE * CW; idx += 1024) {
        int i = idx / CW, d = idx - i * CW;
        float s = 0.0f;
        if (d < TAPS) {
            int c = i - BW + d;
            if (c >= 0 && c < SIZE) {
                const float* Q2 = cb + 5 * SIZE * CBW;
                const float* Q1 = cb + 4 * SIZE * CBW;
                int klo = max(max(i, c) - KBC, 0), khi = min(min(i, c) + KBC, 127);
                for (int k = klo; k <= khi; k++)
                    s += Q2[i * CBW + (k - i + KBC)] * Q1[k * CBW + (c - k + KBC)];
            }
        }
        g_Lb[idx] = s;
    }
    __syncthreads();

    // WbT[d][j] = (E1*E2)[j-BW+d][j]
    for (int idx = tid; idx < SIZE * TAPS; idx += 1024) {
        int d = idx / SIZE, j = idx - d * SIZE;
        float s = 0.0f;
        int r = j - BW + d;
        if (r >= 0 && r < SIZE) {
            const float* E1 = E, *E2 = E + SIZE * EW;
            int mlo = max(max(r, j) - KBE, 0), mhi = min(min(r, j) + KBE, 127);
            for (int m = mlo; m <= mhi; m++)
                s += E1[r * EW + (m - r + KBE)] * E2[m * EW + (j - m + KBE)];
        }
        g_WbT[idx] = s;
    }
}

// ---------------------------------------------------------------------------
// band_kernel: 2 CTAs per image (64-row strips), 256 threads, 8 rows/warp,
// 2 CTAs/SM (R8's proven occupancy shape). Register sliding window (7 float4),
// Lb via warp-uniform LDG (L2-resident), Wb in 28 registers.
// Per row: 1 LDS.128 + 56 FMA + 6 SHFL + 1 STG.128.
// ---------------------------------------------------------------------------
__device__ __forceinline__ float4 f4fma(float c, float4 w, float4 a) {
    a.x = fmaf(c, w.x, a.x); a.y = fmaf(c, w.y, a.y);
    a.z = fmaf(c, w.z, a.z); a.w = fmaf(c, w.w, a.w);
    return a;
}

__global__ void __launch_bounds__(256, 2)
band_kernel(const float* __restrict__ uin, float* __restrict__ uout)
{
    __shared__ float us[UROWS * SIZE];       // 35840 B

    const int tid  = threadIdx.x, w = tid >> 5, lane = tid & 31;
    const int img  = blockIdx.x >> 1;
    const int r0   = (blockIdx.x & 1) * RSTRIP;
    const size_t off = (size_t)img * (SIZE * SIZE);
    const float* src = uin + off;

    // stage u strip rows [r0-3, r0+67) clamped
    #pragma unroll 1
    for (int m = tid; m < UROWS * SIZE / 4; m += 256) {
        int r = m >> 5, c4 = (m & 31) * 4;
        int gr = min(max(r0 - BW + r, 0), SIZE - 1);
        *(float4*)&us[r * SIZE + c4] = *(const float4*)&src[gr * SIZE + c4];
    }

    // per-lane Wb registers, tap-major
    float4 wb4[TAPS];
    #pragma unroll
    for (int d = 0; d < TAPS; d++)
        wb4[d] = *(const float4*)&g_WbT[d * SIZE + 4 * lane];
    __syncthreads();

    const int il0 = w * 8;
    float4 win[TAPS];
    #pragma unroll
    for (int t = 0; t < TAPS - 1; t++)
        win[t] = *(const float4*)&us[(il0 + t) * SIZE + 4 * lane];

    float* dst = uout + off;
    #pragma unroll
    for (int rr = 0; rr < 8; rr++) {
        win[(rr + TAPS - 1) % TAPS] =
            *(const float4*)&us[(il0 + rr + TAPS - 1) * SIZE + 4 * lane];
        const int gi = r0 + il0 + rr;

        // ---- pass 1: T row (Lb warp-uniform LDG) ----
        const float* cr = &g_Lb[gi * CW];
        float4 c0 = *(const float4*)cr;
        float4 c1 = *(const float4*)(cr + 4);
        float4 t4 = make_float4(0.f, 0.f, 0.f, 0.f);
        t4 = f4fma(c0.x, win[(rr + 0) % TAPS], t4);
        t4 = f4fma(c0.y, win[(rr + 1) % TAPS], t4);
        t4 = f4fma(c0.z, win[(rr + 2) % TAPS], t4);
        t4 = f4fma(c0.w, win[(rr + 3) % TAPS], t4);
        t4 = f4fma(c1.x, win[(rr + 4) % TAPS], t4);
        t4 = f4fma(c1.y, win[(rr + 5) % TAPS], t4);
        t4 = f4fma(c1.z, win[(rr + 6) % TAPS], t4);

        // ---- pass 2: row stencil via 6 shuffles (edges hit zero coeffs) ----
        float Tl[10];
        Tl[0] = __shfl_up_sync(0xffffffffu, t4.y, 1);
        Tl[1] = __shfl_up_sync(0xffffffffu, t4.z, 1);
        Tl[2] = __shfl_up_sync(0xffffffffu, t4.w, 1);
        Tl[3] = t4.x; Tl[4] = t4.y; Tl[5] = t4.z; Tl[6] = t4.w;
        Tl[7] = __shfl_down_sync(0xffffffffu, t4.x, 1);
        Tl[8] = __shfl_down_sync(0xffffffffu, t4.y, 1);
        Tl[9] = __shfl_down_sync(0xffffffffu, t4.z, 1);

        float4 o = make_float4(0.f, 0.f, 0.f, 0.f);
        #pragma unroll
        for (int d = 0; d < TAPS; d++) {
            o.x = fmaf(wb4[d].x, Tl[0 + d], o.x);
            o.y = fmaf(wb4[d].y, Tl[1 + d], o.y);
            o.z = fmaf(wb4[d].z, Tl[2 + d], o.z);
            o.w = fmaf(wb4[d].w, Tl[3 + d], o.w);
        }
        *(float4*)&dst[gi * SIZE + 4 * lane] = o;
    }
}

// ---------------------------------------------------------------------------
extern "C" void kernel_launch(void* const* d_in, const int* in_sizes, int n_in,
                              void* d_out, int out_size)
{
    const float* u   = (const float*)d_in[0];
    const float* abx = (const float*)d_in[1];
    const float* bby = (const float*)d_in[4];
    const float* atx = (const float*)d_in[5];
    const float* bty = (const float*)d_in[8];
    const float* aqx = (const float*)d_in[9];
    const float* bqy = (const float*)d_in[12];
    float* out = (float*)d_out;

    const int smem_so = (5 * SIZE + 2 * 5 * 130 + 5 * SIZE * GW + SIZE * CBW)
                        * (int)sizeof(float);                                   // 46672
    const int smem_s3 = (6 * SIZE * CBW + 2 * SIZE * EW) * (int)sizeof(float);  // 90112

    cudaFuncSetAttribute(setup_ops_kernel, cudaFuncAttributeMaxDynamicSharedMemorySize, smem_so);
    cudaFuncSetAttribute(setup3_kernel,    cudaFuncAttributeMaxDynamicSharedMemorySize, smem_s3);

    const int batch = out_size / (SIZE * SIZE);   // 2048

    setup_ops_kernel<<<6, 128, smem_so>>>(abx, atx, aqx, bby, bty, bqy);
    setup3_kernel<<<1, 1024, smem_s3>>>();
    band_kernel<<<batch * 2, 256>>>(u, out);
}

// round 11
// speedup vs baseline: 1.3274x; 1.3274x over previous
#include <cuda_runtime.h>
#include <cstdint>

#define SIZE   128
#define EPSF   1e-6f
#define BW     4            // half bandwidth of final operators
#define TAPS   9            // 2*BW+1
#define CW     12           // padded Lb coeff row width
#define SBW    5            // single-sweep inverse band half-width
#define GW     11           // 2*SBW+1
#define KBC    10           // chain band half-width (5-sweep products)
#define CBW    21           // chain band storage width
#define KBE    12           // E (10-sweep) band half-width
#define EW     25           // E band storage width
#define RSTRIP 64           // rows per band CTA
#define UROWS  (RSTRIP + 2 * BW)   // 72

// ---------------------------------------------------------------------------
// Globals
// ---------------------------------------------------------------------------
__device__ float g_gb[30][SIZE * GW];      // per-sweep banded inverses (hw 5)
// banded chains: 0..3 = X chains C1..C4 (W = C1*C2*C3*C4), 4 = Q1, 5 = Q2 (L = Q2*Q1)
__device__ float g_cb[6][SIZE * CBW];
__device__ float g_Lb[SIZE * CW];          // row-major padded
__device__ float g_WbT[TAPS * SIZE];       // tap-major: WbT[d][j] = W[j-BW+d][j]

// ---------------------------------------------------------------------------
// sweep_inv: 30 CTAs, one per tridiagonal solve. Closed-form banded inverse:
//   (M^-1)_{ij} = (Π co) θ_{i-1} φ_{j+1} / θ_{n-1}
// θ/φ are 128-step two-term recurrences run by lanes 0 / 64 in parallel.
// X sweeps s=0..19 (X-order m0=s: k=m0>>1, t=(k+(m0&1))*DT, dt=DT/2);
// Y sweeps s=20..29 (m0=s-20: t=m0*DT+DT/2, dt=DT).
// ---------------------------------------------------------------------------
__global__ void __launch_bounds__(128, 1)
sweep_inv_kernel(const float* __restrict__ abx, const float* __restrict__ atx,
                 const float* __restrict__ aqx, const float* __restrict__ bby,
                 const float* __restrict__ bty, const float* __restrict__ bqy)
{
    __shared__ float co[SIZE];
    __shared__ float th[SIZE + 1];     // th[i] = theta_{i-1}, i = 0..128
    __shared__ float ph[SIZE + 1];     // ph[j] = phi_j,       j = 0..128

    const int s  = blockIdx.x;
    const bool isY = s >= 20;
    const int m0 = isY ? s - 20 : s;
    const int i  = threadIdx.x;

    float t, dt; const float *bp, *lp, *qp;
    if (isY) { t = m0 * 0.01f + 0.005f;                   dt = 0.01f;  bp = bby; lp = bty; qp = bqy; }
    else     { int k = m0 >> 1; t = (k + (m0 & 1)) * 0.01f; dt = 0.005f; bp = abx; lp = atx; qp = aqx; }

    int im = max(i - 1, 0), ip = min(i + 1, 127);
    float vm = fmaxf(bp[im] + lp[im] * t + qp[im] * t * t, EPSF);
    float vc = fmaxf(bp[i]  + lp[i]  * t + qp[i]  * t * t, EPSF);
    float vp = fmaxf(bp[ip] + lp[ip] * t + qp[ip] * t * t, EPSF);
    co[i] = (vm + vc + vp) * (1.0f / 3.0f) * dt;
    __syncthreads();

    if (i == 0) {
        float t2 = 1.0f;                 // theta_{-1}
        float cprev = co[0];
        float t1 = 1.0f + cprev;         // theta_0 = b_0
        th[0] = 1.0f; th[1] = t1;
        for (int r = 1; r < SIZE; r++) {
            float cr = co[r];
            float br = (r == SIZE - 1) ? (1.0f + cr) : (1.0f + 2.0f * cr);
            float tn = br * t1 - (cr * cprev) * t2;
            th[r + 1] = tn;
            t2 = t1; t1 = tn; cprev = cr;
        }
    } else if (i == 64) {
        float p2 = 1.0f;                 // phi_128
        float cnext = co[SIZE - 1];
        float p1 = 1.0f + cnext;         // phi_127 = b_127
        ph[SIZE] = 1.0f; ph[SIZE - 1] = p1;
        for (int r = SIZE - 2; r >= 0; r--) {
            float cr = co[r];
            float br = (r == 0) ? (1.0f + cr) : (1.0f + 2.0f * cr);
            float pn = br * p1 - (cr * cnext) * p2;
            ph[r] = pn;
            p2 = p1; p1 = pn; cnext = cr;
        }
    }
    __syncthreads();

    const float invthn = 1.0f / th[SIZE];
    #pragma unroll 1
    for (int e = 0; e < GW; e++) {
        int j = i - SBW + e;
        float g = 0.0f;
        if (j >= 0 && j < SIZE) {
            float prod = 1.0f;
            if (i <= j) {
                for (int k = i; k < j; k++) prod *= co[k];
                g = prod * th[i] * ph[j + 1] * invthn;
            } else {
                for (int k = j + 1; k <= i; k++) prod *= co[k];
                g = prod * th[j] * ph[i + 1] * invthn;
            }
        }
        g_gb[s][i * GW + e] = g;
    }
}

// ---------------------------------------------------------------------------
// chain: 6 CTAs of 128 threads; compose 5 banded inverses into one chain band.
// X parts 0..3 (sweeps base..base+4): Acc <- Acc * Gq^T  (Acc[r][c]=Σ Acc[r][k]G[c][k])
// Y parts 4..5: Acc <- Gq * Acc
// ---------------------------------------------------------------------------
__global__ void __launch_bounds__(128, 1) chain_kernel()
{
    __shared__ float acc[SIZE * CBW];
    __shared__ float gsm[SIZE * GW];

    const int part = blockIdx.x;
    const bool isY = part >= 4;
    const int base = isY ? 20 + (part - 4) * 5 : part * 5;
    const int r = threadIdx.x;

    // init: Acc = G0^T (X) or G0 (Y), widened to CBW
    for (int m = r; m < SIZE * GW; m += 128) gsm[m] = g_gb[base][m];
    __syncthreads();
    #pragma unroll 1
    for (int o = 0; o < CBW; o++) {
        int c = r - KBC + o;
        float v = 0.0f;
        if (c >= 0 && c < SIZE && c - r >= -SBW && c - r <= SBW)
            v = isY ? gsm[r * GW + (c - r + SBW)]
                    : gsm[c * GW + (r - c + SBW)];
        acc[r * CBW + o] = v;
    }
    __syncthreads();

    #pragma unroll 1
    for (int q = 1; q < 5; q++) {
        for (int m = r; m < SIZE * GW; m += 128) gsm[m] = g_gb[base + q][m];
        __syncthreads();

        float nw[CBW];
        #pragma unroll 1
        for (int o = 0; o < CBW; o++) {
            int c = r - KBC + o;
            float s = 0.0f;
            if (c >= 0 && c < SIZE) {
                if (isY) {
                    int klo = max(r - SBW, max(c - KBC, 0));
                    int khi = min(r + SBW, min(c + KBC, SIZE - 1));
                    for (int k = klo; k <= khi; k++)
                        s += gsm[r * GW + (k - r + SBW)] * acc[k * CBW + (c - k + KBC)];
                } else {
                    int klo = max(c - SBW, max(r - KBC, 0));
                    int khi = min(c + SBW, min(r + KBC, SIZE - 1));
                    for (int k = klo; k <= khi; k++)
                        s += acc[r * CBW + (k - r + KBC)] * gsm[c * GW + (k - c + SBW)];
                }
            }
            nw[o] = s;
        }
        __syncthreads();
        #pragma unroll 1
        for (int o = 0; o < CBW; o++) acc[r * CBW + o] = nw[o];
        __syncthreads();
    }

    for (int o = 0; o < CBW; o++)
        g_cb[part][r * CBW + o] = acc[r * CBW + o];
}

// ---------------------------------------------------------------------------
// setup3 (validated, R8 verbatim): band composition in one 1024-thread CTA.
// E1 = C1*C2, E2 = C3*C4 (band KBE); Lb = band_BW(Q2*Q1); WbT = band_BW(E1*E2)^T.
// ---------------------------------------------------------------------------
__global__ void __launch_bounds__(1024, 1) setup3_kernel()
{
    extern __shared__ float s3[];
    float* cb = s3;                      // 6*128*21
    float* E  = s3 + 6 * SIZE * CBW;     // 2*128*25
    const int tid = threadIdx.x;

    for (int m = tid; m < 6 * SIZE * CBW; m += 1024)
        cb[m] = ((const float*)g_cb)[m];
    __syncthreads();

    for (int idx = tid; idx < 2 * SIZE * EW; idx += 1024) {
        int e = idx / (SIZE * EW);
        int rem = idx - e * (SIZE * EW);
        int r = rem / EW, d = rem - r * EW;
        int c = r - KBE + d;
        float s = 0.0f;
        if (c >= 0 && c < SIZE) {
            const float* A = cb + (2 * e)     * SIZE * CBW;
            const float* B = cb + (2 * e + 1) * SIZE * CBW;
            int klo = max(max(r, c) - KBC, 0), khi = min(min(r, c) + KBC, 127);
            for (int k = klo; k <= khi; k++)
                s += A[r * CBW + (k - r + KBC)] * B[k * CBW + (c - k + KBC)];
        }
        E[idx] = s;
    }

    // Lb[i][d] = (Q2*Q1)[i][i-BW+d], padded to CW
    for (int idx = tid; idx < SIZE * CW; idx += 1024) {
        int i = idx / CW, d = idx - i * CW;
        float s = 0.0f;
        if (d < TAPS) {
            int c = i - BW + d;
            if (c >= 0 && c < SIZE) {
                const float* Q2 = cb + 5 * SIZE * CBW;
                const float* Q1 = cb + 4 * SIZE * CBW;
                int klo = max(max(i, c) - KBC, 0), khi = min(min(i, c) + KBC, 127);
                for (int k = klo; k <= khi; k++)
                    s += Q2[i * CBW + (k - i + KBC)] * Q1[k * CBW + (c - k + KBC)];
            }
        }
        g_Lb[idx] = s;
    }
    __syncthreads();

    // WbT[d][j] = (E1*E2)[j-BW+d][j]
    for (int idx = tid; idx < SIZE * TAPS; idx += 1024) {
        int d = idx / SIZE, j = idx - d * SIZE;
        float s = 0.0f;
        int r = j - BW + d;
        if (r >= 0 && r < SIZE) {
            const float* E1 = E, *E2 = E + SIZE * EW;
            int mlo = max(max(r, j) - KBE, 0), mhi = min(min(r, j) + KBE, 127);
            for (int m = mlo; m <= mhi; m++)
                s += E1[r * EW + (m - r + KBE)] * E2[m * EW + (j - m + KBE)];
        }
        g_WbT[idx] = s;
    }
}

// ---------------------------------------------------------------------------
// band_kernel (R8 verbatim — measured best ≈69us): 2 CTAs per image,
// 256 threads, 8 rows/warp, 2 CTAs/SM. Register sliding window (9 float4),
// Lb warp-uniform LDG, Wb in 36 regs (tap-major).
// ---------------------------------------------------------------------------
__device__ __forceinline__ float4 f4fma(float c, float4 w, float4 a) {
    a.x = fmaf(c, w.x, a.x); a.y = fmaf(c, w.y, a.y);
    a.z = fmaf(c, w.z, a.z); a.w = fmaf(c, w.w, a.w);
    return a;
}

__global__ void __launch_bounds__(256, 2)
band_kernel(const float* __restrict__ uin, float* __restrict__ uout)
{
    __shared__ float us[UROWS * SIZE];       // 36864 B

    const int tid  = threadIdx.x, w = tid >> 5, lane = tid & 31;
    const int img  = blockIdx.x >> 1;
    const int r0   = (blockIdx.x & 1) * RSTRIP;
    const size_t off = (size_t)img * (SIZE * SIZE);
    const float* src = uin + off;

    // stage u strip rows [r0-4, r0+68) clamped
    #pragma unroll
    for (int q = 0; q < 9; q++) {
        int m = tid + q * 256;
        int r = m >> 5, c4 = (m & 31) * 4;
        int gr = min(max(r0 - BW + r, 0), SIZE - 1);
        *(float4*)&us[r * SIZE + c4] = *(const float4*)&src[gr * SIZE + c4];
    }

    // per-lane Wb registers, tap-major (cols 4*lane..4*lane+3 per tap)
    float4 wb4[TAPS];
    #pragma unroll
    for (int d = 0; d < TAPS; d++)
        wb4[d] = *(const float4*)&g_WbT[d * SIZE + 4 * lane];
    __syncthreads();

    const int il0 = w * 8;
    float4 win[TAPS];
    #pragma unroll
    for (int t = 0; t < TAPS - 1; t++)
        win[t] = *(const float4*)&us[(il0 + t) * SIZE + 4 * lane];

    float* dst = uout + off;
    #pragma unroll
    for (int rr = 0; rr < 8; rr++) {
        win[(rr + TAPS - 1) % TAPS] =
            *(const float4*)&us[(il0 + rr + TAPS - 1) * SIZE + 4 * lane];
        const int gi = r0 + il0 + rr;

        // ---- pass 1: T row (Lb warp-uniform LDG, L2-resident) ----
        const float* cr = &g_Lb[gi * CW];
        float4 c0 = *(const float4*)cr;
        float4 c1 = *(const float4*)(cr + 4);
        float  c8 = cr[8];
        float4 t4 = make_float4(0.f, 0.f, 0.f, 0.f);
        t4 = f4fma(c0.x, win[(rr + 0) % TAPS], t4);
        t4 = f4fma(c0.y, win[(rr + 1) % TAPS], t4);
        t4 = f4fma(c0.z, win[(rr + 2) % TAPS], t4);
        t4 = f4fma(c0.w, win[(rr + 3) % TAPS], t4);
        t4 = f4fma(c1.x, win[(rr + 4) % TAPS], t4);
        t4 = f4fma(c1.y, win[(rr + 5) % TAPS], t4);
        t4 = f4fma(c1.z, win[(rr + 6) % TAPS], t4);
        t4 = f4fma(c1.w, win[(rr + 7) % TAPS], t4);
        t4 = f4fma(c8,   win[(rr + 8) % TAPS], t4);

        // ---- pass 2: row stencil via shuffles (edges hit zero coeffs) ----
        float Tl[12];
        Tl[0] = __shfl_up_sync(0xffffffffu, t4.x, 1);
        Tl[1] = __shfl_up_sync(0xffffffffu, t4.y, 1);
        Tl[2] = __shfl_up_sync(0xffffffffu, t4.z, 1);
        Tl[3] = __shfl_up_sync(0xffffffffu, t4.w, 1);
        Tl[4] = t4.x; Tl[5] = t4.y; Tl[6] = t4.z; Tl[7] = t4.w;
        Tl[8]  = __shfl_down_sync(0xffffffffu, t4.x, 1);
        Tl[9]  = __shfl_down_sync(0xffffffffu, t4.y, 1);
        Tl[10] = __shfl_down_sync(0xffffffffu, t4.z, 1);
        Tl[11] = __shfl_down_sync(0xffffffffu, t4.w, 1);

        float4 o = make_float4(0.f, 0.f, 0.f, 0.f);
        #pragma unroll
        for (int d = 0; d < TAPS; d++) {
            o.x = fmaf(wb4[d].x, Tl[0 + d], o.x);
            o.y = fmaf(wb4[d].y, Tl[1 + d], o.y);
            o.z = fmaf(wb4[d].z, Tl[2 + d], o.z);
            o.w = fmaf(wb4[d].w, Tl[3 + d], o.w);
        }
        *(float4*)&dst[gi * SIZE + 4 * lane] = o;
    }
}

// ---------------------------------------------------------------------------
extern "C" void kernel_launch(void* const* d_in, const int* in_sizes, int n_in,
                              void* d_out, int out_size)
{
    const float* u   = (const float*)d_in[0];
    const float* abx = (const float*)d_in[1];
    const float* bby = (const float*)d_in[4];
    const float* atx = (const float*)d_in[5];
    const float* bty = (const float*)d_in[8];
    const float* aqx = (const float*)d_in[9];
    const float* bqy = (const float*)d_in[12];
    float* out = (float*)d_out;

    const int smem_s3 = (6 * SIZE * CBW + 2 * SIZE * EW) * (int)sizeof(float);  // 90112
    cudaFuncSetAttribute(setup3_kernel, cudaFuncAttributeMaxDynamicSharedMemorySize, smem_s3);

    const int batch = out_size / (SIZE * SIZE);   // 2048

    sweep_inv_kernel<<<30, 128>>>(abx, atx, aqx, bby, bty, bqy);
    chain_kernel<<<6, 128>>>();
    setup3_kernel<<<1, 1024, smem_s3>>>();
    band_kernel<<<batch * 2, 256>>>(u, out);
}